// round 17
// baseline (speedup 1.0000x reference)
#include <cuda_runtime.h>
#include <cuda_bf16.h>
#include <cstdint>

// ============================================================================
// DeformableCurrents: E = sum_{p,q} (w_p.w_q) / (1 + |c_p - c_q|^2)
// over combined src/tar set; f symmetric => triangular tiles (x2 off-diag).
//
// v17 = v16 (dual split-bf16 HMMA + batched inversion + interleaved LDS.128 +
//   shuffle reduction) FULLY FUSED into one launch. The 16 KB smem buffer is
//   time-multiplexed:
//     phase 1: per-thread i-point feature build -> sMem[256][16]
//     phase 2: LDS the A fragment words (no runtime-index spill)
//     phase 3: per-thread j-point feature build -> interleaved uint4 layout
//     phase 4: main loop (unchanged)
//   Kills the 5.4us prep launch at ~+2% block prologue cost.
// ============================================================================

typedef unsigned int u32;

#define THREADS 256
#define G       256          // square tile edge (points)

__device__ double g_partials[4096];
__device__ unsigned int g_done = 0;

__device__ __forceinline__ float rcpf(float x) {
    float r; asm("rcp.approx.ftz.f32 %0, %1;" : "=f"(r) : "f"(x));
    return r;
}

// D(16x8,f32) = A(16x16,bf16) * B(16x8,bf16)
__device__ __forceinline__ void mma_bf16(
    float& c0, float& c1, float& c2, float& c3,
    u32 a0, u32 a1, u32 a2, u32 a3, u32 b0, u32 b1)
{
    float z = 0.f;
    asm volatile(
        "mma.sync.aligned.m16n8k16.row.col.f32.bf16.bf16.f32 "
        "{%0,%1,%2,%3}, {%4,%5,%6,%7}, {%8,%9}, {%10,%11,%12,%13};"
        : "=f"(c0), "=f"(c1), "=f"(c2), "=f"(c3)
        : "r"(a0), "r"(a1), "r"(a2), "r"(a3), "r"(b0), "r"(b1),
          "f"(z), "f"(z), "f"(z), "f"(z));
}

// ---- per-point geometry ------------------------------------------------------
__device__ __forceinline__ void make_point(
    int t, int N, int M,
    const float* __restrict__ verts, const float* __restrict__ tnorm,
    const float* __restrict__ tcent, const int* __restrict__ sidx,
    float& cx, float& cy, float& cz, float& a2,
    float& wx, float& wy, float& wz)
{
    cx = 0.f; cy = 0.f; cz = 0.f; wx = 0.f; wy = 0.f; wz = 0.f;
    if (t < N) {
        int i0 = sidx[3 * t + 0], i1 = sidx[3 * t + 1], i2 = sidx[3 * t + 2];
        float ax = verts[3 * i0], ay = verts[3 * i0 + 1], az = verts[3 * i0 + 2];
        float bx = verts[3 * i1], by = verts[3 * i1 + 1], bz = verts[3 * i1 + 2];
        float gx = verts[3 * i2], gy = verts[3 * i2 + 1], gz = verts[3 * i2 + 2];
        float e1x = ax - bx, e1y = ay - by, e1z = az - bz;
        float e2x = gx - bx, e2y = gy - by, e2z = gz - bz;
        wx = 0.5f * (e1y * e2z - e1z * e2y);
        wy = 0.5f * (e1z * e2x - e1x * e2z);
        wz = 0.5f * (e1x * e2y - e1y * e2x);
        cx = (ax + bx + gx) * (1.0f / 3.0f);
        cy = (ay + by + gy) * (1.0f / 3.0f);
        cz = (az + bz + gz) * (1.0f / 3.0f);
    } else if (t < N + M) {
        int j = t - N;
        cx = tcent[3 * j];  cy = tcent[3 * j + 1];  cz = tcent[3 * j + 2];
        wx = -tnorm[3 * j]; wy = -tnorm[3 * j + 1]; wz = -tnorm[3 * j + 2];
    }
    a2 = cx * cx + cy * cy + cz * cz;
}

__device__ __forceinline__ unsigned short bfb(float x) {
    __nv_bfloat16 h = __float2bfloat16(x);
    return *(unsigned short*)&h;
}
__device__ __forceinline__ float bff(unsigned short b) {
    __nv_bfloat16 h = *(__nv_bfloat16*)&b;
    return __bfloat162float(h);
}
__device__ __forceinline__ u32 pk(unsigned short lo, unsigned short hi) {
    return (u32)lo | ((u32)hi << 16);
}

// ---- split-bf16 feature builder (A row-major, B col-major words) ---------------
__device__ __forceinline__ void build_features(
    float cx, float cy, float cz, float a2, float wx, float wy, float wz,
    u32 Ad[8], u32 An[8], u32 Bd[8], u32 Bn[8])
{
    // denominator: D = 1 + a_i + b_j - 2 c_i.c_j  (split c = h + l)
    unsigned short hx = bfb(cx), hy = bfb(cy), hz = bfb(cz);
    float hxf = bff(hx), hyf = bff(hy), hzf = bff(hz);
    unsigned short lx = bfb(cx - hxf), ly = bfb(cy - hyf), lz = bfb(cz - hzf);
    unsigned short m2hx = bfb(-2.f * hxf), m2hy = bfb(-2.f * hyf), m2hz = bfb(-2.f * hzf);
    unsigned short m2lx = bfb(-2.f * bff(lx)), m2ly = bfb(-2.f * bff(ly)),
                   m2lz = bfb(-2.f * bff(lz));
    unsigned short ah = bfb(a2), al = bfb(a2 - bff(ah));
    float bden = 1.f + a2;
    unsigned short bh = bfb(bden), bl = bfb(bden - bff(bh));
    unsigned short one = bfb(1.f), zz = 0;

    Ad[0] = pk(m2hx, m2hy); Ad[1] = pk(m2hz, m2lx);
    Ad[2] = pk(m2ly, m2lz); Ad[3] = pk(m2hx, m2hy);
    Ad[4] = pk(m2hz, ah);   Ad[5] = pk(al, one);
    Ad[6] = pk(one, zz);    Ad[7] = 0;

    Bd[0] = pk(hx, hy);  Bd[1] = pk(hz, hx);
    Bd[2] = pk(hy, hz);  Bd[3] = pk(lx, ly);
    Bd[4] = pk(lz, one); Bd[5] = pk(one, bh);
    Bd[6] = pk(bl, zz);  Bd[7] = 0;

    // numerator: w.w' = hh' + lh' + hl' (split w = h + l)
    unsigned short hwx = bfb(wx), hwy = bfb(wy), hwz = bfb(wz);
    unsigned short lwx = bfb(wx - bff(hwx)), lwy = bfb(wy - bff(hwy)),
                   lwz = bfb(wz - bff(hwz));

    An[0] = pk(hwx, hwy); An[1] = pk(hwz, lwx);
    An[2] = pk(lwy, lwz); An[3] = pk(hwx, hwy);
    An[4] = pk(hwz, zz);  An[5] = 0;
    An[6] = 0;            An[7] = 0;

    Bn[0] = pk(hwx, hwy); Bn[1] = pk(hwz, hwx);
    Bn[2] = pk(hwy, hwz); Bn[3] = pk(lwx, lwy);
    Bn[4] = pk(lwz, zz);  Bn[5] = 0;
    Bn[6] = 0;            Bn[7] = 0;
}

// ---- fused kernel: 256x256 triangular tiles, dual HMMA, batched inversion ------
__global__ __launch_bounds__(THREADS)
void fused_kernel(const float* __restrict__ verts,
                  const float* __restrict__ tnorm,
                  const float* __restrict__ tcent,
                  const int*   __restrict__ sidx,
                  int N, int M, int T, int nBlocks,
                  float* __restrict__ out)
{
    // 16 KB, time-multiplexed: phase 1-2 = i-features [256][16],
    // phase 3-4 = interleaved j-features (uint4[G*4])
    __shared__ __align__(16) u32 sMem[G * 16];
    __shared__ double swsum[8];
    __shared__ int s_last;

    const int tid = threadIdx.x;
    const int wid = tid >> 5;
    const int lid = tid & 31;
    const int gid = lid >> 2;     // groupID 0..7
    const int tig = lid & 3;      // thread-in-group 0..3

    // block -> (ti, tj) triangular
    int b = blockIdx.x, ti = 0, row = T;
    while (b >= row) { b -= row; ti++; row--; }
    const int tj = ti + b;
    const double scale = (ti == tj) ? 1.0 : 2.0;
    const int Ibase = ti * G;
    const int Jbase = tj * G;

    // ---- phase 1: per-thread i-point features -> sMem[tid][0..15] ----
    {
        float cx, cy, cz, a2, wx, wy, wz;
        make_point(Ibase + tid, N, M, verts, tnorm, tcent, sidx,
                   cx, cy, cz, a2, wx, wy, wz);
        u32 Ad[8], An[8], Bd[8], Bn[8];
        build_features(cx, cy, cz, a2, wx, wy, wz, Ad, An, Bd, Bn);
        u32* s = &sMem[tid * 16];
#pragma unroll
        for (int k = 0; k < 8; k++) { s[k] = Ad[k]; s[k + 8] = An[k]; }
    }
    __syncthreads();

    // ---- phase 2: load A fragments (2 strips of 16 rows per warp) ----
    u32 ad[2][4], an[2][4];
#pragma unroll
    for (int s = 0; s < 2; s++) {
        int lr0 = s * 128 + wid * 16 + gid;
        int lr1 = lr0 + 8;
        ad[s][0] = sMem[lr0 * 16 + tig];
        ad[s][1] = sMem[lr1 * 16 + tig];
        ad[s][2] = sMem[lr0 * 16 + tig + 4];
        ad[s][3] = sMem[lr1 * 16 + tig + 4];
        an[s][0] = sMem[lr0 * 16 + 8 + tig];
        an[s][1] = sMem[lr1 * 16 + 8 + tig];
        an[s][2] = sMem[lr0 * 16 + 8 + tig + 4];
        an[s][3] = sMem[lr1 * 16 + 8 + tig + 4];
    }
    __syncthreads();

    // ---- phase 3: per-thread j-point features -> interleaved uint4 layout ----
    {
        float cx, cy, cz, a2, wx, wy, wz;
        make_point(Jbase + tid, N, M, verts, tnorm, tcent, sidx,
                   cx, cy, cz, a2, wx, wy, wz);
        u32 Ad[8], An[8], Bd[8], Bn[8];
        build_features(cx, cy, cz, a2, wx, wy, wz, Ad, An, Bd, Bn);
        uint4* sB = (uint4*)sMem;
#pragma unroll
        for (int k = 0; k < 4; k++)
            sB[tid * 4 + k] = make_uint4(Bd[k], Bd[k + 4], Bn[k], Bn[k + 4]);
    }
    __syncthreads();

    // ---- phase 4: main loop (identical to v16) ----
    float acc0 = 0.f, acc1 = 0.f, acc2 = 0.f, acc3 = 0.f;
    const uint4* bptr = &((const uint4*)sMem)[gid * 4 + tig];
#pragma unroll 8
    for (int jt = 0; jt < G / 8; jt++) {           // 32 j-subtiles of 8 cols
        const uint4 bf = bptr[jt * 32];            // single conflict-free LDS.128
#pragma unroll
        for (int s = 0; s < 2; s++) {
            float c0, c1, c2, c3, e0, e1, e2, e3;
            mma_bf16(c0, c1, c2, c3, ad[s][0], ad[s][1], ad[s][2], ad[s][3],
                     bf.x, bf.y);
            mma_bf16(e0, e1, e2, e3, an[s][0], an[s][1], an[s][2], an[s][3],
                     bf.z, bf.w);
            // batched inversion: 2 MUFU for 4 denominators
            float rp01 = rcpf(c0 * c1);
            float rp23 = rcpf(c2 * c3);
            acc0 = fmaf(e0, rp01 * c1, acc0);
            acc1 = fmaf(e1, rp01 * c0, acc1);
            acc2 = fmaf(e2, rp23 * c3, acc2);
            acc3 = fmaf(e3, rp23 * c2, acc3);
        }
    }

    // deterministic reduction: warp shuffle tree (fixed lanes), then warp 0
    double e = (((double)acc0 + (double)acc1) + ((double)acc2 + (double)acc3))
               * scale;
#pragma unroll
    for (int off = 16; off > 0; off >>= 1)
        e += __shfl_down_sync(0xFFFFFFFFu, e, off);
    if (lid == 0) swsum[wid] = e;
    __syncthreads();

    if (wid == 0) {
        double v = (lid < 8) ? swsum[lid] : 0.0;
#pragma unroll
        for (int off = 4; off > 0; off >>= 1)
            v += __shfl_down_sync(0xFFFFFFFFu, v, off);
        if (lid == 0) {
            g_partials[blockIdx.x] = v;
            __threadfence();
            unsigned int ticket = atomicAdd(&g_done, 1u);
            s_last = (ticket == (unsigned int)(nBlocks - 1)) ? 1 : 0;
        }
    }
    __syncthreads();

    // last block: fixed-order deterministic final reduction
    if (s_last) {
        __shared__ double rbuf[THREADS];
        double fs = 0.0;
        for (int k = tid; k < nBlocks; k += THREADS)
            fs += g_partials[k];
        rbuf[tid] = fs;
        __syncthreads();
#pragma unroll
        for (int off = THREADS / 2; off > 0; off >>= 1) {
            if (tid < off) rbuf[tid] += rbuf[tid + off];
            __syncthreads();
        }
        if (tid == 0) {
            out[0] = (float)rbuf[0];
            g_done = 0;   // self-restore for next graph replay
        }
    }
}

// ----------------------------------------------------------------------------
extern "C" void kernel_launch(void* const* d_in, const int* in_sizes, int n_in,
                              void* d_out, int out_size)
{
    const float* verts = (const float*)d_in[0];   // src_vertices  (V,3)
    const float* tnorm = (const float*)d_in[1];   // tar_normals   (M,3)
    const float* tcent = (const float*)d_in[2];   // tar_centers   (M,3)
    const int*   sidx  = (const int*)  d_in[3];   // src_indices   (N,3)

    const int N = in_sizes[3] / 3;
    const int M = in_sizes[1] / 3;
    const int total = N + M;
    const int total_pad = ((total + G - 1) / G) * G;
    const int T = total_pad / G;                  // 64 for 16384 points

    const int nBlocks = T * (T + 1) / 2;          // 2080
    fused_kernel<<<nBlocks, THREADS>>>(verts, tnorm, tcent, sidx,
                                       N, M, T, nBlocks, (float*)d_out);
}